// round 8
// baseline (speedup 1.0000x reference)
#include <cuda_runtime.h>
#include <cuda_fp16.h>
#include <cstdint>
#include <cstddef>

// Fixed problem sizes
#define NN 100000
#define NR 8
#define DD 128
#define EE 800000
#define NW 9                       // 8 relations + root
#define SEG (NN * NR)              // 800000 segments (dst,rel)
#define NTILES 782                 // ceil(NN/128)
#define NBLK1 782                  // ceil(SEG/1024) chunks for scans
#define XSH 136                    // smem row stride in halfs

#define ABH (128 * XSH)            // 17408 halfs per tile buffer
// smem layout (bytes): As | W0 | W1 | bias | srp
#define OFF_BIAS (3 * ABH * 2)             // 104448
#define OFF_RP   (OFF_BIAS + 512)          // 104960
#define SMEMB    (OFF_RP + 1032 * 4)       // 109088 -> 2 CTAs/SM

// ---------------------------------------------------------------------------
// Device scratch
// ---------------------------------------------------------------------------
__device__ __half g_xh[(size_t)NN * DD];      // 25.6 MB emb fp16
__device__ __half g_x1h[(size_t)NN * DD];     // 25.6 MB relu(layer1) fp16
__device__ __half g_Wh[2 * NW * DD * DD];     // both layers W[w][k][o] fp16
__device__ int    g_cnt[SEG];
__device__ int    g_rowptr[SEG + 1];
__device__ int    g_dpos[SEG];
__device__ int    g_bsum[NBLK1];
__device__ int    g_esrc[EE];                 // src node, sorted by (dst,rel)

// ---------------------------------------------------------------------------
// PTX helpers
// ---------------------------------------------------------------------------
__device__ __forceinline__ uint32_t sptr(const void* p) {
    return (uint32_t)__cvta_generic_to_shared(p);
}
__device__ __forceinline__ void ldsm4(uint32_t* r, uint32_t addr) {
    asm volatile("ldmatrix.sync.aligned.m8n8.x4.shared.b16 {%0,%1,%2,%3}, [%4];"
                 : "=r"(r[0]), "=r"(r[1]), "=r"(r[2]), "=r"(r[3]) : "r"(addr));
}
__device__ __forceinline__ void ldsm4t(uint32_t* r, uint32_t addr) {
    asm volatile("ldmatrix.sync.aligned.m8n8.x4.trans.shared.b16 {%0,%1,%2,%3}, [%4];"
                 : "=r"(r[0]), "=r"(r[1]), "=r"(r[2]), "=r"(r[3]) : "r"(addr));
}
__device__ __forceinline__ void mma_f16(float* d, const uint32_t* a, uint32_t b0, uint32_t b1) {
    asm volatile(
        "mma.sync.aligned.m16n8k16.row.col.f32.f16.f16.f32 "
        "{%0,%1,%2,%3}, {%4,%5,%6,%7}, {%8,%9}, {%0,%1,%2,%3};"
        : "+f"(d[0]), "+f"(d[1]), "+f"(d[2]), "+f"(d[3])
        : "r"(a[0]), "r"(a[1]), "r"(a[2]), "r"(a[3]), "r"(b0), "r"(b1));
}
__device__ __forceinline__ void cp_async16(uint32_t smem_addr, const void* gptr) {
    asm volatile("cp.async.cg.shared.global [%0], [%1], 16;" :: "r"(smem_addr), "l"(gptr));
}
#define CP_COMMIT() asm volatile("cp.async.commit_group;" ::: "memory")
#define CP_WAIT(n)  asm volatile("cp.async.wait_group %0;" :: "n"(n) : "memory")

__device__ __forceinline__ void addrow(float* af, uint4 q0, uint4 q1) {
    const __half2* h0 = (const __half2*)&q0;
    const __half2* h1 = (const __half2*)&q1;
#pragma unroll
    for (int j = 0; j < 4; j++) {
        float2 f = __half22float2(h0[j]);
        af[2 * j] += f.x; af[2 * j + 1] += f.y;
        float2 g = __half22float2(h1[j]);
        af[8 + 2 * j] += g.x; af[8 + 2 * j + 1] += g.y;
    }
}

// ---------------------------------------------------------------------------
// Preprocessing
// ---------------------------------------------------------------------------
// init: zero cnt + emb->fp16 + both layers' weights, one kernel
__global__ void init_kernel(const float* __restrict__ emb,
                            const float* __restrict__ c1, const float* __restrict__ b1,
                            const float* __restrict__ r1, const float* __restrict__ c2,
                            const float* __restrict__ b2, const float* __restrict__ r2) {
    int i = blockIdx.x * blockDim.x + threadIdx.x;       // 3.2M threads
    if (i < SEG) g_cnt[i] = 0;
    if (i < NN * DD / 4) {
        float4 v = *((const float4*)emb + i);
        __half2* p = (__half2*)(g_xh + (size_t)i * 4);
        p[0] = __floats2half2_rn(v.x, v.y);
        p[1] = __floats2half2_rn(v.z, v.w);
    }
    if (i < 2 * NW * DD * DD) {
        int layer = i >= NW * DD * DD;
        int id = i - layer * NW * DD * DD;
        const float* comp = layer ? c2 : c1;
        const float* basis = layer ? b2 : b1;
        const float* root = layer ? r2 : r1;
        int w = id >> 14;
        int rem = id & 16383;
        int k = rem >> 7, o = rem & 127;
        float v;
        if (w < NR) {
            v = 0.f;
#pragma unroll
            for (int b = 0; b < 8; b++)
                v += comp[w * 8 + b] * basis[((size_t)b * DD + k) * DD + o];
        } else {
            v = root[k * DD + o];
        }
        g_Wh[i] = __float2half_rn(v);
    }
}

__global__ void count_kernel(const int* __restrict__ ei, const int* __restrict__ et) {
    int e = blockIdx.x * blockDim.x + threadIdx.x;
    if (e < EE) atomicAdd(&g_cnt[ei[EE + e] * NR + et[e]], 1);
}

// per-1024-chunk sums of g_cnt -> g_bsum[NBLK1]
__global__ void scan1_kernel() {
    __shared__ int sc[256];
    int base = blockIdx.x * 1024;
    int s = 0;
#pragma unroll
    for (int r = 0; r < 4; r++) {
        int i = base + r * 256 + threadIdx.x;
        s += (i < SEG) ? g_cnt[i] : 0;
    }
    sc[threadIdx.x] = s;
    __syncthreads();
    for (int off = 128; off > 0; off >>= 1) {
        if (threadIdx.x < off) sc[threadIdx.x] += sc[threadIdx.x + off];
        __syncthreads();
    }
    if (threadIdx.x == 0) g_bsum[blockIdx.x] = sc[0];
}

__global__ void scan2_kernel() {     // single-round shuffle scan (NBLK1 <= 1024)
    __shared__ int wsum[32];
    int tid = threadIdx.x;
    int v = (tid < NBLK1) ? g_bsum[tid] : 0;
    int x = v;
#pragma unroll
    for (int off = 1; off < 32; off <<= 1) {
        int t = __shfl_up_sync(0xffffffffu, x, off);
        if ((tid & 31) >= off) x += t;
    }
    if ((tid & 31) == 31) wsum[tid >> 5] = x;
    __syncthreads();
    if (tid < 32) {
        int y = wsum[tid];
#pragma unroll
        for (int off = 1; off < 32; off <<= 1) {
            int t = __shfl_up_sync(0xffffffffu, y, off);
            if (tid >= off) y += t;
        }
        wsum[tid] = y;
    }
    __syncthreads();
    int incl = x + ((tid >= 32) ? wsum[(tid >> 5) - 1] : 0);
    if (tid < NBLK1) g_bsum[tid] = incl - v;     // exclusive
    if (tid == 0) g_rowptr[SEG] = EE;
}

// rowptr + fill cursors: block covers 1024 segs, 4 consecutive per thread
__global__ void scan3_kernel() {
    __shared__ int wsum[8];
    int tid = threadIdx.x, lane = tid & 31, warp = tid >> 5;
    int base = blockIdx.x * 1024;
    int i4 = base + tid * 4;
    int4 c = make_int4(0, 0, 0, 0);
    if (i4 + 3 < SEG) c = *(const int4*)(g_cnt + i4);
    else {
        if (i4 + 0 < SEG) c.x = g_cnt[i4 + 0];
        if (i4 + 1 < SEG) c.y = g_cnt[i4 + 1];
        if (i4 + 2 < SEG) c.z = g_cnt[i4 + 2];
        if (i4 + 3 < SEG) c.w = g_cnt[i4 + 3];
    }
    int s = c.x + c.y + c.z + c.w;
    int x = s;
#pragma unroll
    for (int off = 1; off < 32; off <<= 1) {
        int t = __shfl_up_sync(0xffffffffu, x, off);
        if (lane >= off) x += t;
    }
    if (lane == 31) wsum[warp] = x;
    __syncthreads();
    if (tid < 32) {
        int y = (tid < 8) ? wsum[tid] : 0;
#pragma unroll
        for (int off = 1; off < 8; off <<= 1) {
            int t = __shfl_up_sync(0xffffffffu, y, off);
            if (tid >= off) y += t;
        }
        if (tid < 8) wsum[tid] = y;
    }
    __syncthreads();
    int excl = (x - s) + ((warp > 0) ? wsum[warp - 1] : 0) + g_bsum[blockIdx.x];
    int4 rp;
    rp.x = excl;
    rp.y = excl + c.x;
    rp.z = excl + c.x + c.y;
    rp.w = excl + c.x + c.y + c.z;
    if (i4 + 3 < SEG) {
        *(int4*)(g_rowptr + i4) = rp;
        *(int4*)(g_dpos + i4) = rp;
    } else {
        if (i4 + 0 < SEG) { g_rowptr[i4 + 0] = rp.x; g_dpos[i4 + 0] = rp.x; }
        if (i4 + 1 < SEG) { g_rowptr[i4 + 1] = rp.y; g_dpos[i4 + 1] = rp.y; }
        if (i4 + 2 < SEG) { g_rowptr[i4 + 2] = rp.z; g_dpos[i4 + 2] = rp.z; }
        if (i4 + 3 < SEG) { g_rowptr[i4 + 3] = rp.w; g_dpos[i4 + 3] = rp.w; }
    }
}

__global__ void fill_kernel(const int* __restrict__ ei, const int* __restrict__ et) {
    int e = blockIdx.x * blockDim.x + threadIdx.x;
    if (e >= EE) return;
    int seg = ei[EE + e] * NR + et[e];
    int pos = atomicAdd(&g_dpos[seg], 1);
    g_esrc[pos] = ei[e];
}

// ---------------------------------------------------------------------------
// Fused kernel (2 CTAs/SM): per 128-dst tile, for each relation build mean-agg
// A-tile in smem (prefetched quarter-warp gather, deg1 via cp.async), MMA
// against double-buffered W; root block staged by cp.async.
// ---------------------------------------------------------------------------
__global__ void __launch_bounds__(256, 2)
fused_kernel(const __half* __restrict__ Xsrc, const __half* __restrict__ Wbase,
             const float* __restrict__ bias, float* __restrict__ out32,
             __half* __restrict__ outh) {
    extern __shared__ char smraw[];
    __half* As = (__half*)smraw;                       // [128][XSH]
    __half* SW = (__half*)smraw + ABH;                 // 2 x [128][XSH]
    float* sbias = (float*)(smraw + OFF_BIAS);         // 128
    int*   srp   = (int*)(smraw + OFF_RP);             // 1025

    const int tid = threadIdx.x, wid = tid >> 5, lane = tid & 31;
    const int row0 = blockIdx.x * 128;
    const int seg0 = row0 * NR;
    const int sub = lane >> 3, sl = lane & 7;
    const uint4 Z4 = make_uint4(0u, 0u, 0u, 0u);

    for (int i = tid; i < 1025; i += 256) {
        int s = seg0 + i;
        srp[i] = (s <= SEG) ? g_rowptr[s] : EE;
    }
    if (tid < 128) sbias[tid] = bias[tid];

    // prefetch W[0]
    for (int c = tid; c < 2048; c += 256) {
        int k = c >> 4, c8 = c & 15;
        cp_async16(sptr(SW + k * XSH + c8 * 8), Wbase + k * DD + c8 * 8);
    }
    CP_COMMIT();
    __syncthreads();   // srp visible

    float acc[2][8][4];
#pragma unroll
    for (int mi = 0; mi < 2; mi++)
#pragma unroll
        for (int ni = 0; ni < 8; ni++)
#pragma unroll
            for (int j = 0; j < 4; j++) acc[mi][ni][j] = 0.f;

    const int m0 = (wid >> 1) * 32, n0 = (wid & 1) * 64;
    const int arow = lane & 15, acol8 = (lane >> 4) * 8;

    for (int w = 0; w < NW; w++) {
        // ---- stage A-tile for this block ----
        if (w < NR) {
            // phase 1: segment heads for all 4 groups (8 independent L2 loads)
            int eb[4], dg[4], s0[4], s1[4];
#pragma unroll
            for (int j = 0; j < 4; j++) {
                int row = wid * 16 + j * 4 + sub;
                int idx = row * NR + w;
                eb[j] = srp[idx];
                dg[j] = srp[idx + 1] - eb[j];
                s0[j] = (dg[j] >= 1) ? g_esrc[eb[j]] : 0;
                s1[j] = (dg[j] >= 2) ? g_esrc[eb[j] + 1] : 0;
            }
            // phase 2: zeros + deg1 cp.asyncs issued early
#pragma unroll
            for (int j = 0; j < 4; j++) {
                int row = wid * 16 + j * 4 + sub;
                __half* dst = As + row * XSH + sl * 16;
                if (dg[j] == 0) {
                    *(uint4*)dst = Z4;
                    *(uint4*)(dst + 8) = Z4;
                } else if (dg[j] == 1) {
                    const __half* srcp = Xsrc + (size_t)s0[j] * DD + sl * 16;
                    cp_async16(sptr(dst), srcp);
                    cp_async16(sptr(dst) + 16, srcp + 8);
                }
            }
            // phase 3: deg>=2 accumulation (first two rows address-ready)
#pragma unroll 1
            for (int j = 0; j < 4; j++) {
                if (dg[j] < 2) continue;
                int row = wid * 16 + j * 4 + sub;
                float af[16];
#pragma unroll
                for (int q = 0; q < 16; q++) af[q] = 0.f;
                {
                    const uint4* p0 = (const uint4*)(Xsrc + (size_t)s0[j] * DD) + sl * 2;
                    const uint4* p1 = (const uint4*)(Xsrc + (size_t)s1[j] * DD) + sl * 2;
                    uint4 a0 = p0[0], a1 = p0[1];
                    uint4 b0 = p1[0], b1 = p1[1];
                    addrow(af, a0, a1);
                    addrow(af, b0, b1);
                }
                int e = eb[j] + 2;
                const int e1 = eb[j] + dg[j];
                for (; e + 2 <= e1; e += 2) {
                    int t0 = g_esrc[e], t1 = g_esrc[e + 1];
                    const uint4* p0 = (const uint4*)(Xsrc + (size_t)t0 * DD) + sl * 2;
                    const uint4* p1 = (const uint4*)(Xsrc + (size_t)t1 * DD) + sl * 2;
                    uint4 a0 = p0[0], a1 = p0[1];
                    uint4 b0 = p1[0], b1 = p1[1];
                    addrow(af, a0, a1);
                    addrow(af, b0, b1);
                }
                if (e < e1) {
                    int t0 = g_esrc[e];
                    const uint4* p0 = (const uint4*)(Xsrc + (size_t)t0 * DD) + sl * 2;
                    addrow(af, p0[0], p0[1]);
                }
                float s = 1.0f / (float)dg[j];
                uint4 o0, o1;
                __half2* h0 = (__half2*)&o0;
                __half2* h1 = (__half2*)&o1;
#pragma unroll
                for (int q = 0; q < 4; q++) {
                    h0[q] = __floats2half2_rn(af[2 * q] * s, af[2 * q + 1] * s);
                    h1[q] = __floats2half2_rn(af[8 + 2 * q] * s, af[8 + 2 * q + 1] * s);
                }
                __half* dst = As + row * XSH + sl * 16;
                *(uint4*)dst = o0;
                *(uint4*)(dst + 8) = o1;
            }
        } else {
            // root block: contiguous rows via cp.async
            for (int c = tid; c < 2048; c += 256) {
                int r = c >> 4, c8 = c & 15;
                int g = row0 + r;
                if (g < NN)
                    cp_async16(sptr(As + r * XSH + c8 * 8), Xsrc + (size_t)g * DD + c8 * 8);
                else
                    *(uint4*)(As + r * XSH + c8 * 8) = Z4;
            }
        }
        CP_COMMIT();   // group: this block's A-tile cp.asyncs (may be empty)

        // ---- prefetch W[w+1], then wait for A-tile + W[w] ----
        if (w + 1 < NW) {
            const __half* srcW = Wbase + (size_t)(w + 1) * DD * DD;
            __half* wd = SW + ((w + 1) & 1) * ABH;
            for (int c = tid; c < 2048; c += 256) {
                int k = c >> 4, c8 = c & 15;
                cp_async16(sptr(wd + k * XSH + c8 * 8), srcW + k * DD + c8 * 8);
            }
            CP_COMMIT();
            CP_WAIT(1);      // all but W[w+1]: A-tile(w) + W(w) complete
        } else {
            CP_WAIT(0);
        }
        __syncthreads();

        // ---- MMA K-block ----
        __half* Wc = SW + (w & 1) * ABH;
#pragma unroll
        for (int k0 = 0; k0 < 128; k0 += 16) {
            uint32_t a[2][4];
#pragma unroll
            for (int mi = 0; mi < 2; mi++)
                ldsm4(a[mi], sptr(As + (m0 + mi * 16 + arow) * XSH + k0 + acol8));
            uint32_t bb[4][4];
#pragma unroll
            for (int np = 0; np < 4; np++)
                ldsm4t(bb[np], sptr(Wc + (k0 + arow) * XSH + n0 + np * 16 + acol8));
#pragma unroll
            for (int mi = 0; mi < 2; mi++)
#pragma unroll
                for (int ni = 0; ni < 8; ni++)
                    mma_f16(acc[mi][ni], a[mi],
                            bb[ni >> 1][(ni & 1) * 2], bb[ni >> 1][(ni & 1) * 2 + 1]);
        }
        __syncthreads();   // done reading As before next staging overwrites it
    }

    // ---- epilogue: single output write ----
#pragma unroll
    for (int mi = 0; mi < 2; mi++) {
#pragma unroll
        for (int part = 0; part < 2; part++) {
            int row = m0 + mi * 16 + (lane >> 2) + part * 8;
            int g = row0 + row;
            if (g < NN) {
                if (out32) {
                    float* base = out32 + (size_t)g * DD;
#pragma unroll
                    for (int ni = 0; ni < 8; ni++) {
                        int col = n0 + ni * 8 + 2 * (lane & 3);
                        float2 v;
                        v.x = acc[mi][ni][part * 2] + sbias[col];
                        v.y = acc[mi][ni][part * 2 + 1] + sbias[col + 1];
                        *(float2*)(base + col) = v;
                    }
                } else {
                    __half* base = outh + (size_t)g * DD;
#pragma unroll
                    for (int ni = 0; ni < 8; ni++) {
                        int col = n0 + ni * 8 + 2 * (lane & 3);
                        float vx = fmaxf(acc[mi][ni][part * 2] + sbias[col], 0.f);
                        float vy = fmaxf(acc[mi][ni][part * 2 + 1] + sbias[col + 1], 0.f);
                        *(__half2*)(base + col) = __floats2half2_rn(vx, vy);
                    }
                }
            }
        }
    }
}

// ---------------------------------------------------------------------------
extern "C" void kernel_launch(void* const* d_in, const int* in_sizes, int n_in,
                              void* d_out, int out_size) {
    const int*   ei     = (const int*)d_in[0];
    const int*   et     = (const int*)d_in[1];
    const float* emb    = (const float*)d_in[2];
    const float* basis1 = (const float*)d_in[3];
    const float* comp1  = (const float*)d_in[4];
    const float* root1  = (const float*)d_in[5];
    const float* bias1  = (const float*)d_in[6];
    const float* basis2 = (const float*)d_in[7];
    const float* comp2  = (const float*)d_in[8];
    const float* root2  = (const float*)d_in[9];
    const float* bias2  = (const float*)d_in[10];
    float* out = (float*)d_out;

    cudaFuncSetAttribute(fused_kernel, cudaFuncAttributeMaxDynamicSharedMemorySize,
                         SMEMB);

    __half *xh, *x1h, *wh;
    cudaGetSymbolAddress((void**)&xh, g_xh);
    cudaGetSymbolAddress((void**)&x1h, g_x1h);
    cudaGetSymbolAddress((void**)&wh, g_Wh);

    init_kernel<<<12500, 256>>>(emb, comp1, basis1, root1, comp2, basis2, root2);
    count_kernel<<<3125, 256>>>(ei, et);
    scan1_kernel<<<NBLK1, 256>>>();
    scan2_kernel<<<1, 1024>>>();
    scan3_kernel<<<NBLK1, 256>>>();
    fill_kernel<<<3125, 256>>>(ei, et);

    // layer 1: g_xh -> relu -> g_x1h (fp16)
    fused_kernel<<<NTILES, 256, SMEMB>>>(xh, wh, bias1, nullptr, x1h);
    // layer 2: g_x1h -> out (fp32 + bias)
    fused_kernel<<<NTILES, 256, SMEMB>>>(x1h, wh + NW * DD * DD, bias2, out, nullptr);
}

// round 9
// speedup vs baseline: 1.0575x; 1.0575x over previous
#include <cuda_runtime.h>
#include <cuda_fp16.h>
#include <cstdint>
#include <cstddef>

// Fixed problem sizes
#define NN 100000
#define NR 8
#define DD 128
#define EE 800000
#define NW 9                       // 8 relations + root
#define SEG (NN * NR)              // 800000 segments (dst,rel)
#define NTILES 782                 // ceil(NN/128)
#define NBLK1 782                  // ceil(SEG/1024) chunks for scans
#define XSH 136                    // smem row stride in halfs

#define ABH (128 * XSH)            // 17408 halfs per tile buffer
// smem layout (bytes): As | W0 | W1 | bias | srp
#define OFF_BIAS (3 * ABH * 2)             // 104448
#define OFF_RP   (OFF_BIAS + 512)          // 104960
#define SMEMB    (OFF_RP + 1032 * 4)       // 109088 -> 2 CTAs/SM

// ---------------------------------------------------------------------------
// Device scratch
// ---------------------------------------------------------------------------
__device__ __half g_xh[(size_t)NN * DD];      // 25.6 MB emb fp16
__device__ __half g_x1h[(size_t)NN * DD];     // 25.6 MB relu(layer1) fp16
__device__ __half g_Wh[2 * NW * DD * DD];     // both layers W[w][k][o] fp16
__device__ int    g_cnt[SEG];
__device__ int    g_rowptr[SEG + 1];
__device__ int    g_dpos[SEG];
__device__ int    g_bsum[NBLK1];
__device__ int    g_esrc[EE];                 // src node, sorted by (dst,rel)

// ---------------------------------------------------------------------------
// PTX helpers
// ---------------------------------------------------------------------------
__device__ __forceinline__ uint32_t sptr(const void* p) {
    return (uint32_t)__cvta_generic_to_shared(p);
}
__device__ __forceinline__ void ldsm4(uint32_t* r, uint32_t addr) {
    asm volatile("ldmatrix.sync.aligned.m8n8.x4.shared.b16 {%0,%1,%2,%3}, [%4];"
                 : "=r"(r[0]), "=r"(r[1]), "=r"(r[2]), "=r"(r[3]) : "r"(addr));
}
__device__ __forceinline__ void ldsm4t(uint32_t* r, uint32_t addr) {
    asm volatile("ldmatrix.sync.aligned.m8n8.x4.trans.shared.b16 {%0,%1,%2,%3}, [%4];"
                 : "=r"(r[0]), "=r"(r[1]), "=r"(r[2]), "=r"(r[3]) : "r"(addr));
}
__device__ __forceinline__ void mma_f16(float* d, const uint32_t* a, uint32_t b0, uint32_t b1) {
    asm volatile(
        "mma.sync.aligned.m16n8k16.row.col.f32.f16.f16.f32 "
        "{%0,%1,%2,%3}, {%4,%5,%6,%7}, {%8,%9}, {%0,%1,%2,%3};"
        : "+f"(d[0]), "+f"(d[1]), "+f"(d[2]), "+f"(d[3])
        : "r"(a[0]), "r"(a[1]), "r"(a[2]), "r"(a[3]), "r"(b0), "r"(b1));
}
__device__ __forceinline__ void cp_async16(uint32_t smem_addr, const void* gptr) {
    asm volatile("cp.async.cg.shared.global [%0], [%1], 16;" :: "r"(smem_addr), "l"(gptr));
}
#define CP_COMMIT() asm volatile("cp.async.commit_group;" ::: "memory")
#define CP_WAIT(n)  asm volatile("cp.async.wait_group %0;" :: "n"(n) : "memory")

__device__ __forceinline__ void addrow(float* af, uint4 q0, uint4 q1) {
    const __half2* h0 = (const __half2*)&q0;
    const __half2* h1 = (const __half2*)&q1;
#pragma unroll
    for (int j = 0; j < 4; j++) {
        float2 f = __half22float2(h0[j]);
        af[2 * j] += f.x; af[2 * j + 1] += f.y;
        float2 g = __half22float2(h1[j]);
        af[8 + 2 * j] += g.x; af[8 + 2 * j + 1] += g.y;
    }
}

// ---------------------------------------------------------------------------
// Preprocessing
// ---------------------------------------------------------------------------
// init: zero cnt + emb->fp16 + both layers' weights, one kernel
__global__ void init_kernel(const float* __restrict__ emb,
                            const float* __restrict__ c1, const float* __restrict__ b1,
                            const float* __restrict__ r1, const float* __restrict__ c2,
                            const float* __restrict__ b2, const float* __restrict__ r2) {
    int i = blockIdx.x * blockDim.x + threadIdx.x;       // 3.2M threads
    if (i < SEG) g_cnt[i] = 0;
    if (i < NN * DD / 4) {
        float4 v = *((const float4*)emb + i);
        __half2* p = (__half2*)(g_xh + (size_t)i * 4);
        p[0] = __floats2half2_rn(v.x, v.y);
        p[1] = __floats2half2_rn(v.z, v.w);
    }
    if (i < 2 * NW * DD * DD) {
        int layer = i >= NW * DD * DD;
        int id = i - layer * NW * DD * DD;
        const float* comp = layer ? c2 : c1;
        const float* basis = layer ? b2 : b1;
        const float* root = layer ? r2 : r1;
        int w = id >> 14;
        int rem = id & 16383;
        int k = rem >> 7, o = rem & 127;
        float v;
        if (w < NR) {
            v = 0.f;
#pragma unroll
            for (int b = 0; b < 8; b++)
                v += comp[w * 8 + b] * basis[((size_t)b * DD + k) * DD + o];
        } else {
            v = root[k * DD + o];
        }
        g_Wh[i] = __float2half_rn(v);
    }
}

__global__ void count_kernel(const int* __restrict__ ei, const int* __restrict__ et) {
    int e = blockIdx.x * blockDim.x + threadIdx.x;
    if (e < EE) atomicAdd(&g_cnt[ei[EE + e] * NR + et[e]], 1);
}

// per-1024-chunk sums of g_cnt -> g_bsum[NBLK1]
__global__ void scan1_kernel() {
    __shared__ int sc[256];
    int base = blockIdx.x * 1024;
    int s = 0;
#pragma unroll
    for (int r = 0; r < 4; r++) {
        int i = base + r * 256 + threadIdx.x;
        s += (i < SEG) ? g_cnt[i] : 0;
    }
    sc[threadIdx.x] = s;
    __syncthreads();
    for (int off = 128; off > 0; off >>= 1) {
        if (threadIdx.x < off) sc[threadIdx.x] += sc[threadIdx.x + off];
        __syncthreads();
    }
    if (threadIdx.x == 0) g_bsum[blockIdx.x] = sc[0];
}

__global__ void scan2_kernel() {     // single-round shuffle scan (NBLK1 <= 1024)
    __shared__ int wsum[32];
    int tid = threadIdx.x;
    int v = (tid < NBLK1) ? g_bsum[tid] : 0;
    int x = v;
#pragma unroll
    for (int off = 1; off < 32; off <<= 1) {
        int t = __shfl_up_sync(0xffffffffu, x, off);
        if ((tid & 31) >= off) x += t;
    }
    if ((tid & 31) == 31) wsum[tid >> 5] = x;
    __syncthreads();
    if (tid < 32) {
        int y = wsum[tid];
#pragma unroll
        for (int off = 1; off < 32; off <<= 1) {
            int t = __shfl_up_sync(0xffffffffu, y, off);
            if (tid >= off) y += t;
        }
        wsum[tid] = y;
    }
    __syncthreads();
    int incl = x + ((tid >= 32) ? wsum[(tid >> 5) - 1] : 0);
    if (tid < NBLK1) g_bsum[tid] = incl - v;     // exclusive
    if (tid == 0) g_rowptr[SEG] = EE;
}

// rowptr + fill cursors: block covers 1024 segs, 4 consecutive per thread
__global__ void scan3_kernel() {
    __shared__ int wsum[8];
    int tid = threadIdx.x, lane = tid & 31, warp = tid >> 5;
    int base = blockIdx.x * 1024;
    int i4 = base + tid * 4;
    int4 c = make_int4(0, 0, 0, 0);
    if (i4 + 3 < SEG) c = *(const int4*)(g_cnt + i4);
    else {
        if (i4 + 0 < SEG) c.x = g_cnt[i4 + 0];
        if (i4 + 1 < SEG) c.y = g_cnt[i4 + 1];
        if (i4 + 2 < SEG) c.z = g_cnt[i4 + 2];
        if (i4 + 3 < SEG) c.w = g_cnt[i4 + 3];
    }
    int s = c.x + c.y + c.z + c.w;
    int x = s;
#pragma unroll
    for (int off = 1; off < 32; off <<= 1) {
        int t = __shfl_up_sync(0xffffffffu, x, off);
        if (lane >= off) x += t;
    }
    if (lane == 31) wsum[warp] = x;
    __syncthreads();
    if (tid < 32) {
        int y = (tid < 8) ? wsum[tid] : 0;
#pragma unroll
        for (int off = 1; off < 8; off <<= 1) {
            int t = __shfl_up_sync(0xffffffffu, y, off);
            if (tid >= off) y += t;
        }
        if (tid < 8) wsum[tid] = y;
    }
    __syncthreads();
    int excl = (x - s) + ((warp > 0) ? wsum[warp - 1] : 0) + g_bsum[blockIdx.x];
    int4 rp;
    rp.x = excl;
    rp.y = excl + c.x;
    rp.z = excl + c.x + c.y;
    rp.w = excl + c.x + c.y + c.z;
    if (i4 + 3 < SEG) {
        *(int4*)(g_rowptr + i4) = rp;
        *(int4*)(g_dpos + i4) = rp;
    } else {
        if (i4 + 0 < SEG) { g_rowptr[i4 + 0] = rp.x; g_dpos[i4 + 0] = rp.x; }
        if (i4 + 1 < SEG) { g_rowptr[i4 + 1] = rp.y; g_dpos[i4 + 1] = rp.y; }
        if (i4 + 2 < SEG) { g_rowptr[i4 + 2] = rp.z; g_dpos[i4 + 2] = rp.z; }
        if (i4 + 3 < SEG) { g_rowptr[i4 + 3] = rp.w; g_dpos[i4 + 3] = rp.w; }
    }
}

__global__ void fill_kernel(const int* __restrict__ ei, const int* __restrict__ et) {
    int e = blockIdx.x * blockDim.x + threadIdx.x;
    if (e >= EE) return;
    int seg = ei[EE + e] * NR + et[e];
    int pos = atomicAdd(&g_dpos[seg], 1);
    g_esrc[pos] = ei[e];
}

// ---------------------------------------------------------------------------
// Fused kernel (R7-verbatim staging, 2 CTAs/SM): per 128-dst tile, for each
// relation build mean-agg A-tile in smem (quarter-warp gather, deg1 via
// cp.async), MMA against double-buffered W; root block staged by cp.async.
// ---------------------------------------------------------------------------
__global__ void __launch_bounds__(256, 2)
fused_kernel(const __half* __restrict__ Xsrc, const __half* __restrict__ Wbase,
             const float* __restrict__ bias, float* __restrict__ out32,
             __half* __restrict__ outh) {
    extern __shared__ char smraw[];
    __half* As = (__half*)smraw;                       // [128][XSH]
    __half* SW = (__half*)smraw + ABH;                 // 2 x [128][XSH]
    float* sbias = (float*)(smraw + OFF_BIAS);         // 128
    int*   srp   = (int*)(smraw + OFF_RP);             // 1025

    const int tid = threadIdx.x, wid = tid >> 5, lane = tid & 31;
    const int row0 = blockIdx.x * 128;
    const int seg0 = row0 * NR;
    const int sub = lane >> 3, sl = lane & 7;
    const uint4 Z4 = make_uint4(0u, 0u, 0u, 0u);

    for (int i = tid; i < 1025; i += 256) {
        int s = seg0 + i;
        srp[i] = (s <= SEG) ? g_rowptr[s] : EE;
    }
    if (tid < 128) sbias[tid] = bias[tid];

    // prefetch W[0]
    for (int c = tid; c < 2048; c += 256) {
        int k = c >> 4, c8 = c & 15;
        cp_async16(sptr(SW + k * XSH + c8 * 8), Wbase + k * DD + c8 * 8);
    }
    CP_COMMIT();
    __syncthreads();   // srp visible

    float acc[2][8][4];
#pragma unroll
    for (int mi = 0; mi < 2; mi++)
#pragma unroll
        for (int ni = 0; ni < 8; ni++)
#pragma unroll
            for (int j = 0; j < 4; j++) acc[mi][ni][j] = 0.f;

    const int m0 = (wid >> 1) * 32, n0 = (wid & 1) * 64;
    const int arow = lane & 15, acol8 = (lane >> 4) * 8;

    for (int w = 0; w < NW; w++) {
        // ---- stage A-tile for this block ----
        if (w < NR) {
#pragma unroll 1
            for (int g4 = 0; g4 < 4; g4++) {
                int row = wid * 16 + g4 * 4 + sub;
                int idx = row * NR + w;
                int e = srp[idx];
                const int e1 = srp[idx + 1];
                const int dg = e1 - e;
                __half* dst = As + row * XSH + sl * 16;
                if (dg == 0) {
                    *(uint4*)dst = Z4;
                    *(uint4*)(dst + 8) = Z4;
                } else if (dg == 1) {
                    // mean of one row == the row: direct global->smem copy
                    int s0 = g_esrc[e];
                    const __half* srcp = Xsrc + (size_t)s0 * DD + sl * 16;
                    cp_async16(sptr(dst), srcp);
                    cp_async16(sptr(dst) + 16, srcp + 8);
                } else {
                    float af[16];
#pragma unroll
                    for (int q = 0; q < 16; q++) af[q] = 0.f;
                    // 2-edge unroll: MLP 4
                    for (; e + 2 <= e1; e += 2) {
                        int s0 = g_esrc[e], s1 = g_esrc[e + 1];
                        const uint4* p0 = (const uint4*)(Xsrc + (size_t)s0 * DD) + sl * 2;
                        const uint4* p1 = (const uint4*)(Xsrc + (size_t)s1 * DD) + sl * 2;
                        uint4 a0 = p0[0], a1 = p0[1];
                        uint4 b0 = p1[0], b1 = p1[1];
                        addrow(af, a0, a1);
                        addrow(af, b0, b1);
                    }
                    if (e < e1) {
                        int s0 = g_esrc[e];
                        const uint4* p0 = (const uint4*)(Xsrc + (size_t)s0 * DD) + sl * 2;
                        addrow(af, p0[0], p0[1]);
                    }
                    float s = 1.0f / (float)dg;
                    uint4 o0, o1;
                    __half2* h0 = (__half2*)&o0;
                    __half2* h1 = (__half2*)&o1;
#pragma unroll
                    for (int q = 0; q < 4; q++) {
                        h0[q] = __floats2half2_rn(af[2 * q] * s, af[2 * q + 1] * s);
                        h1[q] = __floats2half2_rn(af[8 + 2 * q] * s, af[8 + 2 * q + 1] * s);
                    }
                    *(uint4*)dst = o0;
                    *(uint4*)(dst + 8) = o1;
                }
            }
        } else {
            // root block: contiguous rows via cp.async
            for (int c = tid; c < 2048; c += 256) {
                int r = c >> 4, c8 = c & 15;
                int g = row0 + r;
                if (g < NN)
                    cp_async16(sptr(As + r * XSH + c8 * 8), Xsrc + (size_t)g * DD + c8 * 8);
                else
                    *(uint4*)(As + r * XSH + c8 * 8) = Z4;
            }
        }
        CP_COMMIT();   // group: this block's A-tile cp.asyncs (may be empty)

        // ---- prefetch W[w+1], then wait for A-tile + W[w] ----
        if (w + 1 < NW) {
            const __half* srcW = Wbase + (size_t)(w + 1) * DD * DD;
            __half* wd = SW + ((w + 1) & 1) * ABH;
            for (int c = tid; c < 2048; c += 256) {
                int k = c >> 4, c8 = c & 15;
                cp_async16(sptr(wd + k * XSH + c8 * 8), srcW + k * DD + c8 * 8);
            }
            CP_COMMIT();
            CP_WAIT(1);      // all but W[w+1]: A-tile(w) + W(w) complete
        } else {
            CP_WAIT(0);
        }
        __syncthreads();

        // ---- MMA K-block ----
        __half* Wc = SW + (w & 1) * ABH;
#pragma unroll
        for (int k0 = 0; k0 < 128; k0 += 16) {
            uint32_t a[2][4];
#pragma unroll
            for (int mi = 0; mi < 2; mi++)
                ldsm4(a[mi], sptr(As + (m0 + mi * 16 + arow) * XSH + k0 + acol8));
            uint32_t bb[4][4];
#pragma unroll
            for (int np = 0; np < 4; np++)
                ldsm4t(bb[np], sptr(Wc + (k0 + arow) * XSH + n0 + np * 16 + acol8));
#pragma unroll
            for (int mi = 0; mi < 2; mi++)
#pragma unroll
                for (int ni = 0; ni < 8; ni++)
                    mma_f16(acc[mi][ni], a[mi],
                            bb[ni >> 1][(ni & 1) * 2], bb[ni >> 1][(ni & 1) * 2 + 1]);
        }
        __syncthreads();   // done reading As before next staging overwrites it
    }

    // ---- epilogue: single output write ----
#pragma unroll
    for (int mi = 0; mi < 2; mi++) {
#pragma unroll
        for (int part = 0; part < 2; part++) {
            int row = m0 + mi * 16 + (lane >> 2) + part * 8;
            int g = row0 + row;
            if (g < NN) {
                if (out32) {
                    float* base = out32 + (size_t)g * DD;
#pragma unroll
                    for (int ni = 0; ni < 8; ni++) {
                        int col = n0 + ni * 8 + 2 * (lane & 3);
                        float2 v;
                        v.x = acc[mi][ni][part * 2] + sbias[col];
                        v.y = acc[mi][ni][part * 2 + 1] + sbias[col + 1];
                        *(float2*)(base + col) = v;
                    }
                } else {
                    __half* base = outh + (size_t)g * DD;
#pragma unroll
                    for (int ni = 0; ni < 8; ni++) {
                        int col = n0 + ni * 8 + 2 * (lane & 3);
                        float vx = fmaxf(acc[mi][ni][part * 2] + sbias[col], 0.f);
                        float vy = fmaxf(acc[mi][ni][part * 2 + 1] + sbias[col + 1], 0.f);
                        *(__half2*)(base + col) = __floats2half2_rn(vx, vy);
                    }
                }
            }
        }
    }
}

// ---------------------------------------------------------------------------
extern "C" void kernel_launch(void* const* d_in, const int* in_sizes, int n_in,
                              void* d_out, int out_size) {
    const int*   ei     = (const int*)d_in[0];
    const int*   et     = (const int*)d_in[1];
    const float* emb    = (const float*)d_in[2];
    const float* basis1 = (const float*)d_in[3];
    const float* comp1  = (const float*)d_in[4];
    const float* root1  = (const float*)d_in[5];
    const float* bias1  = (const float*)d_in[6];
    const float* basis2 = (const float*)d_in[7];
    const float* comp2  = (const float*)d_in[8];
    const float* root2  = (const float*)d_in[9];
    const float* bias2  = (const float*)d_in[10];
    float* out = (float*)d_out;

    cudaFuncSetAttribute(fused_kernel, cudaFuncAttributeMaxDynamicSharedMemorySize,
                         SMEMB);

    __half *xh, *x1h, *wh;
    cudaGetSymbolAddress((void**)&xh, g_xh);
    cudaGetSymbolAddress((void**)&x1h, g_x1h);
    cudaGetSymbolAddress((void**)&wh, g_Wh);

    init_kernel<<<12500, 256>>>(emb, comp1, basis1, root1, comp2, basis2, root2);
    count_kernel<<<3125, 256>>>(ei, et);
    scan1_kernel<<<NBLK1, 256>>>();
    scan2_kernel<<<1, 1024>>>();
    scan3_kernel<<<NBLK1, 256>>>();
    fill_kernel<<<3125, 256>>>(ei, et);

    // layer 1: g_xh -> relu -> g_x1h (fp16)
    fused_kernel<<<NTILES, 256, SMEMB>>>(xh, wh, bias1, nullptr, x1h);
    // layer 2: g_x1h -> out (fp32 + bias)
    fused_kernel<<<NTILES, 256, SMEMB>>>(x1h, wh + NW * DD * DD, bias2, out, nullptr);
}

// round 10
// speedup vs baseline: 1.0593x; 1.0018x over previous
#include <cuda_runtime.h>
#include <cuda_fp16.h>
#include <cstdint>
#include <cstddef>

// Fixed problem sizes
#define NN 100000
#define NR 8
#define DD 128
#define EE 800000
#define NW 9                       // 8 relations + root
#define SEG (NN * NR)              // 800000 segments (dst,rel)
#define NTILES 782                 // ceil(NN/128)
#define NBLK1 782                  // ceil(SEG/1024) chunks for scans
#define XSH 136                    // smem row stride in halfs

#define ABH (128 * XSH)            // 17408 halfs per tile buffer
// smem layout (bytes): As | W0 | W1 | bias | srp
#define OFF_BIAS (3 * ABH * 2)             // 104448
#define OFF_RP   (OFF_BIAS + 512)          // 104960
#define SMEMB    (OFF_RP + 1032 * 4)       // 109088 -> 2 CTAs/SM

// ---------------------------------------------------------------------------
// Device scratch
// ---------------------------------------------------------------------------
__device__ __half g_xh[(size_t)NN * DD];      // 25.6 MB emb fp16
__device__ __half g_x1h[(size_t)NN * DD];     // 25.6 MB relu(layer1) fp16
__device__ __half g_Wh[2 * NW * DD * DD];     // both layers W[w][k][o] fp16
__device__ int    g_cnt[SEG];
__device__ int    g_rowptr[SEG + 1];
__device__ int    g_dpos[SEG];
__device__ int    g_bsum[NBLK1];
__device__ int    g_esrc[EE];                 // src node, sorted by (dst,rel)

// ---------------------------------------------------------------------------
// PTX helpers
// ---------------------------------------------------------------------------
__device__ __forceinline__ uint32_t sptr(const void* p) {
    return (uint32_t)__cvta_generic_to_shared(p);
}
__device__ __forceinline__ void ldsm4(uint32_t* r, uint32_t addr) {
    asm volatile("ldmatrix.sync.aligned.m8n8.x4.shared.b16 {%0,%1,%2,%3}, [%4];"
                 : "=r"(r[0]), "=r"(r[1]), "=r"(r[2]), "=r"(r[3]) : "r"(addr));
}
__device__ __forceinline__ void ldsm4t(uint32_t* r, uint32_t addr) {
    asm volatile("ldmatrix.sync.aligned.m8n8.x4.trans.shared.b16 {%0,%1,%2,%3}, [%4];"
                 : "=r"(r[0]), "=r"(r[1]), "=r"(r[2]), "=r"(r[3]) : "r"(addr));
}
__device__ __forceinline__ void mma_f16(float* d, const uint32_t* a, uint32_t b0, uint32_t b1) {
    asm volatile(
        "mma.sync.aligned.m16n8k16.row.col.f32.f16.f16.f32 "
        "{%0,%1,%2,%3}, {%4,%5,%6,%7}, {%8,%9}, {%0,%1,%2,%3};"
        : "+f"(d[0]), "+f"(d[1]), "+f"(d[2]), "+f"(d[3])
        : "r"(a[0]), "r"(a[1]), "r"(a[2]), "r"(a[3]), "r"(b0), "r"(b1));
}
__device__ __forceinline__ void cp_async16(uint32_t smem_addr, const void* gptr) {
    asm volatile("cp.async.cg.shared.global [%0], [%1], 16;" :: "r"(smem_addr), "l"(gptr));
}
#define CP_COMMIT() asm volatile("cp.async.commit_group;" ::: "memory")
#define CP_WAIT(n)  asm volatile("cp.async.wait_group %0;" :: "n"(n) : "memory")

__device__ __forceinline__ void addrow(float* af, uint4 q0, uint4 q1) {
    const __half2* h0 = (const __half2*)&q0;
    const __half2* h1 = (const __half2*)&q1;
#pragma unroll
    for (int j = 0; j < 4; j++) {
        float2 f = __half22float2(h0[j]);
        af[2 * j] += f.x; af[2 * j + 1] += f.y;
        float2 g = __half22float2(h1[j]);
        af[8 + 2 * j] += g.x; af[8 + 2 * j + 1] += g.y;
    }
}

// ---------------------------------------------------------------------------
// Preprocessing
// ---------------------------------------------------------------------------
// init: zero cnt + emb->fp16 + both layers' weights, one kernel
__global__ void init_kernel(const float* __restrict__ emb,
                            const float* __restrict__ c1, const float* __restrict__ b1,
                            const float* __restrict__ r1, const float* __restrict__ c2,
                            const float* __restrict__ b2, const float* __restrict__ r2) {
    int i = blockIdx.x * blockDim.x + threadIdx.x;       // 3.2M threads
    if (i < SEG) g_cnt[i] = 0;
    if (i < NN * DD / 4) {
        float4 v = *((const float4*)emb + i);
        __half2* p = (__half2*)(g_xh + (size_t)i * 4);
        p[0] = __floats2half2_rn(v.x, v.y);
        p[1] = __floats2half2_rn(v.z, v.w);
    }
    if (i < 2 * NW * DD * DD) {
        int layer = i >= NW * DD * DD;
        int id = i - layer * NW * DD * DD;
        const float* comp = layer ? c2 : c1;
        const float* basis = layer ? b2 : b1;
        const float* root = layer ? r2 : r1;
        int w = id >> 14;
        int rem = id & 16383;
        int k = rem >> 7, o = rem & 127;
        float v;
        if (w < NR) {
            v = 0.f;
#pragma unroll
            for (int b = 0; b < 8; b++)
                v += comp[w * 8 + b] * basis[((size_t)b * DD + k) * DD + o];
        } else {
            v = root[k * DD + o];
        }
        g_Wh[i] = __float2half_rn(v);
    }
}

__global__ void count_kernel(const int* __restrict__ ei, const int* __restrict__ et) {
    int e = blockIdx.x * blockDim.x + threadIdx.x;
    if (e < EE) atomicAdd(&g_cnt[ei[EE + e] * NR + et[e]], 1);
}

// per-1024-chunk sums of g_cnt -> g_bsum[NBLK1]
__global__ void scan1_kernel() {
    __shared__ int sc[256];
    int base = blockIdx.x * 1024;
    int s = 0;
#pragma unroll
    for (int r = 0; r < 4; r++) {
        int i = base + r * 256 + threadIdx.x;
        s += (i < SEG) ? g_cnt[i] : 0;
    }
    sc[threadIdx.x] = s;
    __syncthreads();
    for (int off = 128; off > 0; off >>= 1) {
        if (threadIdx.x < off) sc[threadIdx.x] += sc[threadIdx.x + off];
        __syncthreads();
    }
    if (threadIdx.x == 0) g_bsum[blockIdx.x] = sc[0];
}

// rowptr + fill cursors; computes its own carry from raw g_bsum (no scan2)
__global__ void scan3_kernel() {
    __shared__ int wsum[8];
    __shared__ int wsum2[8];
    __shared__ int carry_s;
    int tid = threadIdx.x, lane = tid & 31, warp = tid >> 5;
    int base = blockIdx.x * 1024;

    // carry = sum of raw g_bsum[0 .. blockIdx.x)
    int part = 0;
    for (int b = tid; b < blockIdx.x; b += 256) part += g_bsum[b];
#pragma unroll
    for (int off = 16; off > 0; off >>= 1)
        part += __shfl_down_sync(0xffffffffu, part, off);
    if (lane == 0) wsum2[warp] = part;

    // per-thread 4 consecutive counts
    int i4 = base + tid * 4;
    int4 c = make_int4(0, 0, 0, 0);
    if (i4 + 3 < SEG) c = *(const int4*)(g_cnt + i4);
    else {
        if (i4 + 0 < SEG) c.x = g_cnt[i4 + 0];
        if (i4 + 1 < SEG) c.y = g_cnt[i4 + 1];
        if (i4 + 2 < SEG) c.z = g_cnt[i4 + 2];
        if (i4 + 3 < SEG) c.w = g_cnt[i4 + 3];
    }
    int s = c.x + c.y + c.z + c.w;
    int x = s;
#pragma unroll
    for (int off = 1; off < 32; off <<= 1) {
        int t = __shfl_up_sync(0xffffffffu, x, off);
        if (lane >= off) x += t;
    }
    if (lane == 31) wsum[warp] = x;
    __syncthreads();
    if (tid < 32) {
        int y = (tid < 8) ? wsum[tid] : 0;
#pragma unroll
        for (int off = 1; off < 8; off <<= 1) {
            int t = __shfl_up_sync(0xffffffffu, y, off);
            if (tid >= off) y += t;
        }
        if (tid < 8) wsum[tid] = y;
    }
    if (tid == 32) {   // warp 1: fold the 8 warp-partials into carry
        int cc = 0;
#pragma unroll
        for (int u = 0; u < 8; u++) cc += wsum2[u];
        carry_s = cc;
    }
    __syncthreads();
    int excl = (x - s) + ((warp > 0) ? wsum[warp - 1] : 0) + carry_s;
    int4 rp;
    rp.x = excl;
    rp.y = excl + c.x;
    rp.z = excl + c.x + c.y;
    rp.w = excl + c.x + c.y + c.z;
    if (i4 + 3 < SEG) {
        *(int4*)(g_rowptr + i4) = rp;
        *(int4*)(g_dpos + i4) = rp;
    } else {
        if (i4 + 0 < SEG) { g_rowptr[i4 + 0] = rp.x; g_dpos[i4 + 0] = rp.x; }
        if (i4 + 1 < SEG) { g_rowptr[i4 + 1] = rp.y; g_dpos[i4 + 1] = rp.y; }
        if (i4 + 2 < SEG) { g_rowptr[i4 + 2] = rp.z; g_dpos[i4 + 2] = rp.z; }
        if (i4 + 3 < SEG) { g_rowptr[i4 + 3] = rp.w; g_dpos[i4 + 3] = rp.w; }
    }
    if (blockIdx.x == 0 && tid == 0) g_rowptr[SEG] = EE;
}

__global__ void fill_kernel(const int* __restrict__ ei, const int* __restrict__ et) {
    int e = blockIdx.x * blockDim.x + threadIdx.x;
    if (e >= EE) return;
    int seg = ei[EE + e] * NR + et[e];
    int pos = atomicAdd(&g_dpos[seg], 1);
    g_esrc[pos] = ei[e];
}

// ---------------------------------------------------------------------------
// Fused kernel (2 CTAs/SM): per 128-dst tile, for each relation build mean-agg
// A-tile in smem (quarter-warp gather, deg1 via cp.async), MMA against
// double-buffered W; root block staged by cp.async. Relation order is rotated
// by 4 for odd waves so co-resident CTAs anti-phase their gather/MMA.
// ---------------------------------------------------------------------------
__global__ void __launch_bounds__(256, 2)
fused_kernel(const __half* __restrict__ Xsrc, const __half* __restrict__ Wbase,
             const float* __restrict__ bias, float* __restrict__ out32,
             __half* __restrict__ outh) {
    extern __shared__ char smraw[];
    __half* As = (__half*)smraw;                       // [128][XSH]
    __half* SW = (__half*)smraw + ABH;                 // 2 x [128][XSH]
    float* sbias = (float*)(smraw + OFF_BIAS);         // 128
    int*   srp   = (int*)(smraw + OFF_RP);             // 1025

    const int tid = threadIdx.x, wid = tid >> 5, lane = tid & 31;
    const int row0 = blockIdx.x * 128;
    const int seg0 = row0 * NR;
    const int sub = lane >> 3, sl = lane & 7;
    const int ph = ((blockIdx.x / 148) & 1) * 4;       // wave anti-phase
    const uint4 Z4 = make_uint4(0u, 0u, 0u, 0u);

    for (int i = tid; i < 1025; i += 256) {
        int s = seg0 + i;
        srp[i] = (s <= SEG) ? g_rowptr[s] : EE;
    }
    if (tid < 128) sbias[tid] = bias[tid];

    // prefetch W for the first (rotated) relation block
    {
        const __half* srcW = Wbase + (size_t)(ph & 7) * DD * DD;
        for (int c = tid; c < 2048; c += 256) {
            int k = c >> 4, c8 = c & 15;
            cp_async16(sptr(SW + k * XSH + c8 * 8), srcW + k * DD + c8 * 8);
        }
    }
    CP_COMMIT();
    __syncthreads();   // srp visible

    float acc[2][8][4];
#pragma unroll
    for (int mi = 0; mi < 2; mi++)
#pragma unroll
        for (int ni = 0; ni < 8; ni++)
#pragma unroll
            for (int j = 0; j < 4; j++) acc[mi][ni][j] = 0.f;

    const int m0 = (wid >> 1) * 32, n0 = (wid & 1) * 64;
    const int arow = lane & 15, acol8 = (lane >> 4) * 8;

    for (int w = 0; w < NW; w++) {
        const int rw = (w < NR) ? ((w + ph) & 7) : NR;   // rotated relation id
        // ---- stage A-tile for this block ----
        if (w < NR) {
#pragma unroll 1
            for (int g4 = 0; g4 < 4; g4++) {
                int row = wid * 16 + g4 * 4 + sub;
                int idx = row * NR + rw;
                int e = srp[idx];
                const int e1 = srp[idx + 1];
                const int dg = e1 - e;
                __half* dst = As + row * XSH + sl * 16;
                if (dg == 0) {
                    *(uint4*)dst = Z4;
                    *(uint4*)(dst + 8) = Z4;
                } else if (dg == 1) {
                    // mean of one row == the row: direct global->smem copy
                    int s0 = g_esrc[e];
                    const __half* srcp = Xsrc + (size_t)s0 * DD + sl * 16;
                    cp_async16(sptr(dst), srcp);
                    cp_async16(sptr(dst) + 16, srcp + 8);
                } else {
                    float af[16];
#pragma unroll
                    for (int q = 0; q < 16; q++) af[q] = 0.f;
                    // 2-edge unroll: MLP 4
                    for (; e + 2 <= e1; e += 2) {
                        int s0 = g_esrc[e], s1 = g_esrc[e + 1];
                        const uint4* p0 = (const uint4*)(Xsrc + (size_t)s0 * DD) + sl * 2;
                        const uint4* p1 = (const uint4*)(Xsrc + (size_t)s1 * DD) + sl * 2;
                        uint4 a0 = p0[0], a1 = p0[1];
                        uint4 b0 = p1[0], b1 = p1[1];
                        addrow(af, a0, a1);
                        addrow(af, b0, b1);
                    }
                    if (e < e1) {
                        int s0 = g_esrc[e];
                        const uint4* p0 = (const uint4*)(Xsrc + (size_t)s0 * DD) + sl * 2;
                        addrow(af, p0[0], p0[1]);
                    }
                    float s = 1.0f / (float)dg;
                    uint4 o0, o1;
                    __half2* h0 = (__half2*)&o0;
                    __half2* h1 = (__half2*)&o1;
#pragma unroll
                    for (int q = 0; q < 4; q++) {
                        h0[q] = __floats2half2_rn(af[2 * q] * s, af[2 * q + 1] * s);
                        h1[q] = __floats2half2_rn(af[8 + 2 * q] * s, af[8 + 2 * q + 1] * s);
                    }
                    *(uint4*)dst = o0;
                    *(uint4*)(dst + 8) = o1;
                }
            }
        } else {
            // root block: contiguous rows via cp.async
            for (int c = tid; c < 2048; c += 256) {
                int r = c >> 4, c8 = c & 15;
                int g = row0 + r;
                if (g < NN)
                    cp_async16(sptr(As + r * XSH + c8 * 8), Xsrc + (size_t)g * DD + c8 * 8);
                else
                    *(uint4*)(As + r * XSH + c8 * 8) = Z4;
            }
        }
        CP_COMMIT();   // group: this block's A-tile cp.asyncs (may be empty)

        // ---- prefetch W for next (rotated) block, then wait for A + W(w) ----
        if (w + 1 < NW) {
            const int rn = (w + 1 < NR) ? ((w + 1 + ph) & 7) : NR;
            const __half* srcW = Wbase + (size_t)rn * DD * DD;
            __half* wd = SW + ((w + 1) & 1) * ABH;
            for (int c = tid; c < 2048; c += 256) {
                int k = c >> 4, c8 = c & 15;
                cp_async16(sptr(wd + k * XSH + c8 * 8), srcW + k * DD + c8 * 8);
            }
            CP_COMMIT();
            CP_WAIT(1);      // all but W[w+1]: A-tile(w) + W(w) complete
        } else {
            CP_WAIT(0);
        }
        __syncthreads();

        // ---- MMA K-block ----
        __half* Wc = SW + (w & 1) * ABH;
#pragma unroll
        for (int k0 = 0; k0 < 128; k0 += 16) {
            uint32_t a[2][4];
#pragma unroll
            for (int mi = 0; mi < 2; mi++)
                ldsm4(a[mi], sptr(As + (m0 + mi * 16 + arow) * XSH + k0 + acol8));
            uint32_t bb[4][4];
#pragma unroll
            for (int np = 0; np < 4; np++)
                ldsm4t(bb[np], sptr(Wc + (k0 + arow) * XSH + n0 + np * 16 + acol8));
#pragma unroll
            for (int mi = 0; mi < 2; mi++)
#pragma unroll
                for (int ni = 0; ni < 8; ni++)
                    mma_f16(acc[mi][ni], a[mi],
                            bb[ni >> 1][(ni & 1) * 2], bb[ni >> 1][(ni & 1) * 2 + 1]);
        }
        __syncthreads();   // done reading As before next staging overwrites it
    }

    // ---- epilogue: single output write ----
#pragma unroll
    for (int mi = 0; mi < 2; mi++) {
#pragma unroll
        for (int part = 0; part < 2; part++) {
            int row = m0 + mi * 16 + (lane >> 2) + part * 8;
            int g = row0 + row;
            if (g < NN) {
                if (out32) {
                    float* base = out32 + (size_t)g * DD;
#pragma unroll
                    for (int ni = 0; ni < 8; ni++) {
                        int col = n0 + ni * 8 + 2 * (lane & 3);
                        float2 v;
                        v.x = acc[mi][ni][part * 2] + sbias[col];
                        v.y = acc[mi][ni][part * 2 + 1] + sbias[col + 1];
                        *(float2*)(base + col) = v;
                    }
                } else {
                    __half* base = outh + (size_t)g * DD;
#pragma unroll
                    for (int ni = 0; ni < 8; ni++) {
                        int col = n0 + ni * 8 + 2 * (lane & 3);
                        float vx = fmaxf(acc[mi][ni][part * 2] + sbias[col], 0.f);
                        float vy = fmaxf(acc[mi][ni][part * 2 + 1] + sbias[col + 1], 0.f);
                        *(__half2*)(base + col) = __floats2half2_rn(vx, vy);
                    }
                }
            }
        }
    }
}

// ---------------------------------------------------------------------------
extern "C" void kernel_launch(void* const* d_in, const int* in_sizes, int n_in,
                              void* d_out, int out_size) {
    const int*   ei     = (const int*)d_in[0];
    const int*   et     = (const int*)d_in[1];
    const float* emb    = (const float*)d_in[2];
    const float* basis1 = (const float*)d_in[3];
    const float* comp1  = (const float*)d_in[4];
    const float* root1  = (const float*)d_in[5];
    const float* bias1  = (const float*)d_in[6];
    const float* basis2 = (const float*)d_in[7];
    const float* comp2  = (const float*)d_in[8];
    const float* root2  = (const float*)d_in[9];
    const float* bias2  = (const float*)d_in[10];
    float* out = (float*)d_out;

    cudaFuncSetAttribute(fused_kernel, cudaFuncAttributeMaxDynamicSharedMemorySize,
                         SMEMB);

    __half *xh, *x1h, *wh;
    cudaGetSymbolAddress((void**)&xh, g_xh);
    cudaGetSymbolAddress((void**)&x1h, g_x1h);
    cudaGetSymbolAddress((void**)&wh, g_Wh);

    init_kernel<<<12500, 256>>>(emb, comp1, basis1, root1, comp2, basis2, root2);
    count_kernel<<<3125, 256>>>(ei, et);
    scan1_kernel<<<NBLK1, 256>>>();
    scan3_kernel<<<NBLK1, 256>>>();
    fill_kernel<<<3125, 256>>>(ei, et);

    // layer 1: g_xh -> relu -> g_x1h (fp16)
    fused_kernel<<<NTILES, 256, SMEMB>>>(xh, wh, bias1, nullptr, x1h);
    // layer 2: g_x1h -> out (fp32 + bias)
    fused_kernel<<<NTILES, 256, SMEMB>>>(x1h, wh + NW * DD * DD, bias2, out, nullptr);
}